// round 1
// baseline (speedup 1.0000x reference)
#include <cuda_runtime.h>

#define NSN 50000
#define NE  1600000
#define CIN 11
#define CP  12      // padded feature stride (11 -> 12, 48B rows, 16B-aligned)
#define HD  64

// ---------------- scratch (static __device__, no allocation) ----------------
__device__ float g_agg[4][NSN*HD];     // layer-2 aggregators; layer-1 uses first NSN*CP floats per type
__device__ int   g_cnt[4][NSN];        // in-degree per edge type
__device__ float g_xpad[2][NSN*CP];    // padded input features (shop, public)
__device__ float g_h[2][NSN*HD];       // layer-1 output
__device__ float g_h2[2][NSN*HD];      // layer-2 output

__device__ __forceinline__ void red_v4(float* p, float a, float b, float c, float d) {
    asm volatile("red.global.add.v4.f32 [%0], {%1, %2, %3, %4};"
                 :: "l"(__cvta_generic_to_global(p)),
                    "f"(a), "f"(b), "f"(c), "f"(d)
                 : "memory");
}

// ---------------- init: pad features, zero layer-1 agg + counts -------------
__global__ void k_init(const float* __restrict__ xs, const float* __restrict__ xp) {
    int i = blockIdx.x * 256 + threadIdx.x;
    if (i < NSN * CP) {
        int n = i / CP, c = i % CP;
        g_xpad[0][i] = (c < CIN) ? xs[n * CIN + c] : 0.f;
        g_xpad[1][i] = (c < CIN) ? xp[n * CIN + c] : 0.f;
        #pragma unroll
        for (int t = 0; t < 4; t++) g_agg[t][i] = 0.f;
    }
    if (i < NSN) {
        #pragma unroll
        for (int t = 0; t < 4; t++) g_cnt[t][i] = 0;
    }
}

// ---------------- degree counts ---------------------------------------------
__global__ void k_count(const int* __restrict__ d0, const int* __restrict__ d1,
                        const int* __restrict__ d2, const int* __restrict__ d3) {
    int e = blockIdx.x * 256 + threadIdx.x;   // NE divisible by 256
    atomicAdd(&g_cnt[0][d0[e]], 1);
    atomicAdd(&g_cnt[1][d1[e]], 1);
    atomicAdd(&g_cnt[2][d2[e]], 1);
    atomicAdd(&g_cnt[3][d3[e]], 1);
}

// ---------------- layer-1 edge scatter (12 floats / edge) -------------------
__global__ void k_scatter1(const int* __restrict__ e0, const int* __restrict__ e1,
                           const int* __restrict__ e2, const int* __restrict__ e3) {
    int t = blockIdx.y;
    int e = blockIdx.x * 256 + threadIdx.x;
    const int* ei = (t == 0) ? e0 : (t == 1) ? e1 : (t == 2) ? e2 : e3;
    int stype = t >> 1;                        // 0,1 -> shop src ; 2,3 -> public src
    int s = ei[e];
    int d = ei[NE + e];
    const float4* xr = (const float4*)(g_xpad[stype] + (size_t)s * CP);
    float4 a = xr[0], b = xr[1], c = xr[2];    // c.w is the zero pad
    float* dst = g_agg[t] + (size_t)d * CP;
    red_v4(dst,     a.x, a.y, a.z, a.w);
    red_v4(dst + 4, b.x, b.y, b.z, b.w);
    red_v4(dst + 8, c.x, c.y, c.z, c.w);
}

// ---------------- layer-1 node update ---------------------------------------
__global__ void __launch_bounds__(256) k_l1nodes(const float* __restrict__ w1l,
                                                 const float* __restrict__ b1l,
                                                 const float* __restrict__ w1r) {
    int nt = blockIdx.y;             // 0 = shop, 1 = public
    int ta = nt ? 1 : 0;             // shop: (ss=0, ps=2) ; public: (sp=1, pp=3)
    int tb = nt ? 3 : 2;
    __shared__ float sA[CIN * HD], sB[CIN * HD], sR[CIN * HD], sb[HD];
    for (int i = threadIdx.x; i < CIN * HD; i += 256) {
        sA[i] = w1l[ta * CIN * HD + i];
        sB[i] = w1l[tb * CIN * HD + i];
        sR[i] = w1r[ta * CIN * HD + i] + w1r[tb * CIN * HD + i];
    }
    if (threadIdx.x < HD)
        sb[threadIdx.x] = b1l[ta * HD + threadIdx.x] + b1l[tb * HD + threadIdx.x];
    __syncthreads();

    int n = blockIdx.x * 256 + threadIdx.x;
    if (n >= NSN) return;
    int ca = g_cnt[ta][n], cb = g_cnt[tb][n];
    float inva = 1.f / (float)(ca > 0 ? ca : 1);
    float invb = 1.f / (float)(cb > 0 ? cb : 1);

    float acc[HD];
    #pragma unroll
    for (int o = 0; o < HD; o++) acc[o] = sb[o];

    const float* A = g_agg[ta] + (size_t)n * CP;
    const float* B = g_agg[tb] + (size_t)n * CP;
    const float* X = g_xpad[nt] + (size_t)n * CP;
    #pragma unroll
    for (int i = 0; i < CIN; i++) {
        float ma = A[i] * inva, mb = B[i] * invb, xv = X[i];
        const float4* wa = (const float4*)(sA + i * HD);
        const float4* wb = (const float4*)(sB + i * HD);
        const float4* wr = (const float4*)(sR + i * HD);
        #pragma unroll
        for (int o4 = 0; o4 < HD / 4; o4++) {
            float4 a = wa[o4], b = wb[o4], r = wr[o4];
            acc[o4 * 4 + 0] += ma * a.x + mb * b.x + xv * r.x;
            acc[o4 * 4 + 1] += ma * a.y + mb * b.y + xv * r.y;
            acc[o4 * 4 + 2] += ma * a.z + mb * b.z + xv * r.z;
            acc[o4 * 4 + 3] += ma * a.w + mb * b.w + xv * r.w;
        }
    }
    float4* out = (float4*)(g_h[nt] + (size_t)n * HD);
    #pragma unroll
    for (int o4 = 0; o4 < HD / 4; o4++) {
        float4 v;
        v.x = fmaxf(acc[o4 * 4 + 0], 0.f);
        v.y = fmaxf(acc[o4 * 4 + 1], 0.f);
        v.z = fmaxf(acc[o4 * 4 + 2], 0.f);
        v.w = fmaxf(acc[o4 * 4 + 3], 0.f);
        out[o4] = v;
    }
}

// ---------------- zero layer-2 aggregators ----------------------------------
__global__ void k_zero2() {
    int i = blockIdx.x * 256 + threadIdx.x;   // NSN*HD divisible by 256
    #pragma unroll
    for (int t = 0; t < 4; t++) g_agg[t][i] = 0.f;
}

// ---------------- layer-2 edge scatter (16 threads / edge, 256B rows) -------
__global__ void k_scatter2(const int* __restrict__ e0, const int* __restrict__ e1,
                           const int* __restrict__ e2, const int* __restrict__ e3) {
    int t = blockIdx.y;
    int gid = blockIdx.x * 256 + threadIdx.x;
    int e = gid >> 4;
    int j = gid & 15;
    const int* ei = (t == 0) ? e0 : (t == 1) ? e1 : (t == 2) ? e2 : e3;
    int stype = t >> 1;
    int s = ei[e];
    int d = ei[NE + e];
    float4 v = ((const float4*)(g_h[stype] + (size_t)s * HD))[j];
    red_v4(g_agg[t] + (size_t)d * HD + j * 4, v.x, v.y, v.z, v.w);
}

// ---------------- layer-2 node update ---------------------------------------
__global__ void __launch_bounds__(256) k_l2nodes(const float* __restrict__ w2l,
                                                 const float* __restrict__ b2l,
                                                 const float* __restrict__ w2r) {
    int nt = blockIdx.y;
    int ta = nt ? 1 : 0;
    int tb = nt ? 3 : 2;
    __shared__ float sA[HD * HD], sB[HD * HD], sR[HD * HD];   // 48 KB
    for (int i = threadIdx.x; i < HD * HD; i += 256) {
        sA[i] = w2l[ta * HD * HD + i];
        sB[i] = w2l[tb * HD * HD + i];
        sR[i] = w2r[ta * HD * HD + i] + w2r[tb * HD * HD + i];
    }
    __syncthreads();

    int n = blockIdx.x * 256 + threadIdx.x;
    if (n >= NSN) return;
    int ca = g_cnt[ta][n], cb = g_cnt[tb][n];
    float inva = 1.f / (float)(ca > 0 ? ca : 1);
    float invb = 1.f / (float)(cb > 0 ? cb : 1);

    float acc[HD];
    #pragma unroll
    for (int o = 0; o < HD; o++) acc[o] = b2l[ta * HD + o] + b2l[tb * HD + o];

    const float4* A4 = (const float4*)(g_agg[ta] + (size_t)n * HD);
    const float4* B4 = (const float4*)(g_agg[tb] + (size_t)n * HD);
    const float4* H4 = (const float4*)(g_h[nt] + (size_t)n * HD);

    #pragma unroll
    for (int g = 0; g < HD / 4; g++) {
        float4 mav = A4[g], mbv = B4[g], hhv = H4[g];
        float fa[4] = {mav.x * inva, mav.y * inva, mav.z * inva, mav.w * inva};
        float fb[4] = {mbv.x * invb, mbv.y * invb, mbv.z * invb, mbv.w * invb};
        float fh[4] = {hhv.x, hhv.y, hhv.z, hhv.w};
        #pragma unroll
        for (int u = 0; u < 4; u++) {
            int k = g * 4 + u;
            const float4* wa = (const float4*)(sA + k * HD);
            const float4* wb = (const float4*)(sB + k * HD);
            const float4* wr = (const float4*)(sR + k * HD);
            #pragma unroll
            for (int o4 = 0; o4 < HD / 4; o4++) {
                float4 a = wa[o4], b = wb[o4], r = wr[o4];
                acc[o4 * 4 + 0] += fa[u] * a.x + fb[u] * b.x + fh[u] * r.x;
                acc[o4 * 4 + 1] += fa[u] * a.y + fb[u] * b.y + fh[u] * r.y;
                acc[o4 * 4 + 2] += fa[u] * a.z + fb[u] * b.z + fh[u] * r.z;
                acc[o4 * 4 + 3] += fa[u] * a.w + fb[u] * b.w + fh[u] * r.w;
            }
        }
    }
    float4* out = (float4*)(g_h2[nt] + (size_t)n * HD);
    #pragma unroll
    for (int o4 = 0; o4 < HD / 4; o4++) {
        float4 v;
        v.x = fmaxf(acc[o4 * 4 + 0], 0.f);
        v.y = fmaxf(acc[o4 * 4 + 1], 0.f);
        v.z = fmaxf(acc[o4 * 4 + 2], 0.f);
        v.w = fmaxf(acc[o4 * 4 + 3], 0.f);
        out[o4] = v;
    }
}

// ---------------- final linear heads ----------------------------------------
__global__ void k_final(const float* __restrict__ wls, const float* __restrict__ bls,
                        const float* __restrict__ wlp, const float* __restrict__ blp,
                        float* __restrict__ out) {
    int n = blockIdx.x * 256 + threadIdx.x;
    if (n >= 2 * NSN) return;
    int nt = (n < NSN) ? 0 : 1;
    int m = nt ? n - NSN : n;
    const float4* h4 = (const float4*)(g_h2[nt] + (size_t)m * HD);
    const float* w = nt ? wlp : wls;
    float acc = nt ? blp[0] : bls[0];
    #pragma unroll
    for (int g = 0; g < 16; g++) {
        float4 v = h4[g];
        acc += v.x * w[g * 4] + v.y * w[g * 4 + 1] + v.z * w[g * 4 + 2] + v.w * w[g * 4 + 3];
    }
    out[n] = acc;
}

// ---------------- launch ----------------------------------------------------
extern "C" void kernel_launch(void* const* d_in, const int* in_sizes, int n_in,
                              void* d_out, int out_size) {
    const float* xs  = (const float*)d_in[0];
    const float* xp  = (const float*)d_in[1];
    const float* w1l = (const float*)d_in[2];
    const float* b1l = (const float*)d_in[3];
    const float* w1r = (const float*)d_in[4];
    const float* w2l = (const float*)d_in[5];
    const float* b2l = (const float*)d_in[6];
    const float* w2r = (const float*)d_in[7];
    const float* wls = (const float*)d_in[8];
    const float* bls = (const float*)d_in[9];
    const float* wlp = (const float*)d_in[10];
    const float* blp = (const float*)d_in[11];
    const int* ss = (const int*)d_in[12];   // ei_ss: [0..NE)=src, [NE..2NE)=dst
    const int* sp = (const int*)d_in[13];
    const int* ps = (const int*)d_in[14];
    const int* pp = (const int*)d_in[15];
    float* out = (float*)d_out;

    k_init<<<(NSN * CP + 255) / 256, 256>>>(xs, xp);
    k_count<<<NE / 256, 256>>>(ss + NE, sp + NE, ps + NE, pp + NE);
    k_scatter1<<<dim3(NE / 256, 4), 256>>>(ss, sp, ps, pp);
    k_l1nodes<<<dim3((NSN + 255) / 256, 2), 256>>>(w1l, b1l, w1r);
    k_zero2<<<(NSN * HD) / 256, 256>>>();
    k_scatter2<<<dim3((NE * 16) / 256, 4), 256>>>(ss, sp, ps, pp);
    k_l2nodes<<<dim3((NSN + 255) / 256, 2), 256>>>(w2l, b2l, w2r);
    k_final<<<(2 * NSN + 255) / 256, 256>>>(wls, bls, wlp, blp, out);
}

// round 2
// speedup vs baseline: 1.3372x; 1.3372x over previous
#include <cuda_runtime.h>

#define NSN 50000
#define NE  1600000
#define CIN 11
#define HD  64

// ---------------- scratch (static __device__, no allocation) ----------------
__device__ int   g_hist[4][NSN];        // in-degree per edge type
__device__ int   g_rowstart[4][NSN];    // CSR row offsets (exclusive scan of hist)
__device__ int   g_cursor[4][NSN];      // fill cursors (copy of rowstart)
__device__ int   g_csr[4][NE];          // CSR source ids, grouped by dst
__device__ float g_mean1[4][NSN*CIN];   // layer-1 mean aggregates
__device__ float g_mean2[4][(size_t)NSN*HD]; // layer-2 mean aggregates
__device__ float g_h[2][(size_t)NSN*HD];     // layer-1 output
__device__ float g_h2[2][(size_t)NSN*HD];    // layer-2 output

// ---------------- zero histogram --------------------------------------------
__global__ void k_zero_hist() {
    int i = blockIdx.x * 256 + threadIdx.x;
    if (i < NSN) {
        #pragma unroll
        for (int t = 0; t < 4; t++) g_hist[t][i] = 0;
    }
}

// ---------------- degree histogram ------------------------------------------
__global__ void k_hist(const int* __restrict__ d0, const int* __restrict__ d1,
                       const int* __restrict__ d2, const int* __restrict__ d3) {
    int e = blockIdx.x * 256 + threadIdx.x;   // NE divisible by 256
    atomicAdd(&g_hist[0][d0[e]], 1);
    atomicAdd(&g_hist[1][d1[e]], 1);
    atomicAdd(&g_hist[2][d2[e]], 1);
    atomicAdd(&g_hist[3][d3[e]], 1);
}

// ---------------- exclusive prefix scan (one block per edge type) -----------
__global__ void __launch_bounds__(1024) k_scan() {
    int t = blockIdx.x;
    int lane = threadIdx.x & 31, warp = threadIdx.x >> 5;
    __shared__ int wsum[32];
    __shared__ int s_carry;
    if (threadIdx.x == 0) s_carry = 0;
    __syncthreads();
    for (int base = 0; base < NSN; base += 1024) {
        int i = base + threadIdx.x;
        int v = (i < NSN) ? g_hist[t][i] : 0;
        int x = v;
        #pragma unroll
        for (int off = 1; off < 32; off <<= 1) {
            int y = __shfl_up_sync(0xffffffffu, x, off);
            if (lane >= off) x += y;
        }
        if (lane == 31) wsum[warp] = x;
        __syncthreads();
        if (warp == 0) {
            int w = wsum[lane];
            #pragma unroll
            for (int off = 1; off < 32; off <<= 1) {
                int y = __shfl_up_sync(0xffffffffu, w, off);
                if (lane >= off) w += y;
            }
            wsum[lane] = w;
        }
        __syncthreads();
        int incl = x + (warp > 0 ? wsum[warp - 1] : 0);
        int carry = s_carry;
        if (i < NSN) {
            int ex = carry + incl - v;
            g_rowstart[t][i] = ex;
            g_cursor[t][i] = ex;
        }
        __syncthreads();
        if (threadIdx.x == 1023) s_carry = carry + wsum[31];
        __syncthreads();
    }
}

// ---------------- CSR fill ---------------------------------------------------
__global__ void k_fill(const int* __restrict__ e0, const int* __restrict__ e1,
                       const int* __restrict__ e2, const int* __restrict__ e3) {
    int t = blockIdx.y;
    int e = blockIdx.x * 256 + threadIdx.x;
    const int* ei = (t == 0) ? e0 : (t == 1) ? e1 : (t == 2) ? e2 : e3;
    int s = ei[e];
    int d = ei[NE + e];
    int pos = atomicAdd(&g_cursor[t][d], 1);
    g_csr[t][pos] = s;
}

// ---------------- layer-1 gather-aggregate (warp per node,type) -------------
__global__ void __launch_bounds__(256) k_agg1(const float* __restrict__ xs,
                                              const float* __restrict__ xp) {
    int t = blockIdx.y;
    const float* x = (t >> 1) ? xp : xs;
    int warp = threadIdx.x >> 5, lane = threadIdx.x & 31;
    int n = blockIdx.x * 8 + warp;
    if (n >= NSN) return;
    int half = lane >> 4;     // 0 or 1: which neighbor of the pair
    int col = lane & 15;      // 0..15, active col < CIN
    int base = g_rowstart[t][n];
    int cnt = g_hist[t][n];
    const int* cs = g_csr[t] + base;
    float acc = 0.f;
    for (int i = half; i < cnt; i += 2) {
        int s = cs[i];
        if (col < CIN) acc += x[(size_t)s * CIN + col];
    }
    acc += __shfl_xor_sync(0xffffffffu, acc, 16);
    float inv = 1.f / (float)(cnt > 0 ? cnt : 1);
    if (half == 0 && col < CIN) g_mean1[t][(size_t)n * CIN + col] = acc * inv;
}

// ---------------- layer-1 node update ---------------------------------------
__global__ void __launch_bounds__(256) k_l1nodes(const float* __restrict__ xs,
                                                 const float* __restrict__ xp,
                                                 const float* __restrict__ w1l,
                                                 const float* __restrict__ b1l,
                                                 const float* __restrict__ w1r) {
    int nt = blockIdx.y;             // 0 = shop, 1 = public
    int ta = nt ? 1 : 0;             // shop: (ss=0, ps=2) ; public: (sp=1, pp=3)
    int tb = nt ? 3 : 2;
    const float* x = nt ? xp : xs;
    __shared__ float sA[CIN * HD], sB[CIN * HD], sR[CIN * HD], sb[HD];
    for (int i = threadIdx.x; i < CIN * HD; i += 256) {
        sA[i] = w1l[ta * CIN * HD + i];
        sB[i] = w1l[tb * CIN * HD + i];
        sR[i] = w1r[ta * CIN * HD + i] + w1r[tb * CIN * HD + i];
    }
    if (threadIdx.x < HD)
        sb[threadIdx.x] = b1l[ta * HD + threadIdx.x] + b1l[tb * HD + threadIdx.x];
    __syncthreads();

    int n = blockIdx.x * 256 + threadIdx.x;
    if (n >= NSN) return;

    float acc[HD];
    #pragma unroll
    for (int o = 0; o < HD; o++) acc[o] = sb[o];

    const float* A = g_mean1[ta] + (size_t)n * CIN;
    const float* B = g_mean1[tb] + (size_t)n * CIN;
    const float* X = x + (size_t)n * CIN;
    #pragma unroll
    for (int i = 0; i < CIN; i++) {
        float ma = A[i], mb = B[i], xv = X[i];
        const float4* wa = (const float4*)(sA + i * HD);
        const float4* wb = (const float4*)(sB + i * HD);
        const float4* wr = (const float4*)(sR + i * HD);
        #pragma unroll
        for (int o4 = 0; o4 < HD / 4; o4++) {
            float4 a = wa[o4], b = wb[o4], r = wr[o4];
            acc[o4 * 4 + 0] += ma * a.x + mb * b.x + xv * r.x;
            acc[o4 * 4 + 1] += ma * a.y + mb * b.y + xv * r.y;
            acc[o4 * 4 + 2] += ma * a.z + mb * b.z + xv * r.z;
            acc[o4 * 4 + 3] += ma * a.w + mb * b.w + xv * r.w;
        }
    }
    float4* out = (float4*)(g_h[nt] + (size_t)n * HD);
    #pragma unroll
    for (int o4 = 0; o4 < HD / 4; o4++) {
        float4 v;
        v.x = fmaxf(acc[o4 * 4 + 0], 0.f);
        v.y = fmaxf(acc[o4 * 4 + 1], 0.f);
        v.z = fmaxf(acc[o4 * 4 + 2], 0.f);
        v.w = fmaxf(acc[o4 * 4 + 3], 0.f);
        out[o4] = v;
    }
}

// ---------------- layer-2 gather-aggregate (warp per node,type) -------------
__global__ void __launch_bounds__(256) k_agg2() {
    int t = blockIdx.y;
    int stype = t >> 1;
    int warp = threadIdx.x >> 5, lane = threadIdx.x & 31;
    int n = blockIdx.x * 8 + warp;
    if (n >= NSN) return;
    int base = g_rowstart[t][n];
    int cnt = g_hist[t][n];
    const int* cs = g_csr[t] + base;
    const float* h = g_h[stype];
    float a0 = 0.f, a1 = 0.f;
    int i = 0;
    for (; i + 2 <= cnt; i += 2) {
        int s0 = cs[i], s1 = cs[i + 1];
        const float* p0 = h + (size_t)s0 * HD;
        const float* p1 = h + (size_t)s1 * HD;
        float v00 = p0[lane], v01 = p0[lane + 32];
        float v10 = p1[lane], v11 = p1[lane + 32];
        a0 += v00 + v10;
        a1 += v01 + v11;
    }
    if (i < cnt) {
        const float* p0 = h + (size_t)cs[i] * HD;
        a0 += p0[lane];
        a1 += p0[lane + 32];
    }
    float inv = 1.f / (float)(cnt > 0 ? cnt : 1);
    g_mean2[t][(size_t)n * HD + lane] = a0 * inv;
    g_mean2[t][(size_t)n * HD + lane + 32] = a1 * inv;
}

// ---------------- layer-2 node update ---------------------------------------
__global__ void __launch_bounds__(256) k_l2nodes(const float* __restrict__ w2l,
                                                 const float* __restrict__ b2l,
                                                 const float* __restrict__ w2r) {
    int nt = blockIdx.y;
    int ta = nt ? 1 : 0;
    int tb = nt ? 3 : 2;
    __shared__ float sA[HD * HD], sB[HD * HD], sR[HD * HD];   // 48 KB
    for (int i = threadIdx.x; i < HD * HD; i += 256) {
        sA[i] = w2l[ta * HD * HD + i];
        sB[i] = w2l[tb * HD * HD + i];
        sR[i] = w2r[ta * HD * HD + i] + w2r[tb * HD * HD + i];
    }
    __syncthreads();

    int n = blockIdx.x * 256 + threadIdx.x;
    if (n >= NSN) return;

    float acc[HD];
    #pragma unroll
    for (int o = 0; o < HD; o++) acc[o] = b2l[ta * HD + o] + b2l[tb * HD + o];

    const float4* A4 = (const float4*)(g_mean2[ta] + (size_t)n * HD);
    const float4* B4 = (const float4*)(g_mean2[tb] + (size_t)n * HD);
    const float4* H4 = (const float4*)(g_h[nt] + (size_t)n * HD);

    #pragma unroll
    for (int g = 0; g < HD / 4; g++) {
        float4 mav = A4[g], mbv = B4[g], hhv = H4[g];
        float fa[4] = {mav.x, mav.y, mav.z, mav.w};
        float fb[4] = {mbv.x, mbv.y, mbv.z, mbv.w};
        float fh[4] = {hhv.x, hhv.y, hhv.z, hhv.w};
        #pragma unroll
        for (int u = 0; u < 4; u++) {
            int k = g * 4 + u;
            const float4* wa = (const float4*)(sA + k * HD);
            const float4* wb = (const float4*)(sB + k * HD);
            const float4* wr = (const float4*)(sR + k * HD);
            #pragma unroll
            for (int o4 = 0; o4 < HD / 4; o4++) {
                float4 a = wa[o4], b = wb[o4], r = wr[o4];
                acc[o4 * 4 + 0] += fa[u] * a.x + fb[u] * b.x + fh[u] * r.x;
                acc[o4 * 4 + 1] += fa[u] * a.y + fb[u] * b.y + fh[u] * r.y;
                acc[o4 * 4 + 2] += fa[u] * a.z + fb[u] * b.z + fh[u] * r.z;
                acc[o4 * 4 + 3] += fa[u] * a.w + fb[u] * b.w + fh[u] * r.w;
            }
        }
    }
    float4* out = (float4*)(g_h2[nt] + (size_t)n * HD);
    #pragma unroll
    for (int o4 = 0; o4 < HD / 4; o4++) {
        float4 v;
        v.x = fmaxf(acc[o4 * 4 + 0], 0.f);
        v.y = fmaxf(acc[o4 * 4 + 1], 0.f);
        v.z = fmaxf(acc[o4 * 4 + 2], 0.f);
        v.w = fmaxf(acc[o4 * 4 + 3], 0.f);
        out[o4] = v;
    }
}

// ---------------- final linear heads ----------------------------------------
__global__ void k_final(const float* __restrict__ wls, const float* __restrict__ bls,
                        const float* __restrict__ wlp, const float* __restrict__ blp,
                        float* __restrict__ out) {
    int n = blockIdx.x * 256 + threadIdx.x;
    if (n >= 2 * NSN) return;
    int nt = (n < NSN) ? 0 : 1;
    int m = nt ? n - NSN : n;
    const float4* h4 = (const float4*)(g_h2[nt] + (size_t)m * HD);
    const float* w = nt ? wlp : wls;
    float acc = nt ? blp[0] : bls[0];
    #pragma unroll
    for (int g = 0; g < 16; g++) {
        float4 v = h4[g];
        acc += v.x * w[g * 4] + v.y * w[g * 4 + 1] + v.z * w[g * 4 + 2] + v.w * w[g * 4 + 3];
    }
    out[n] = acc;
}

// ---------------- launch ----------------------------------------------------
extern "C" void kernel_launch(void* const* d_in, const int* in_sizes, int n_in,
                              void* d_out, int out_size) {
    const float* xs  = (const float*)d_in[0];
    const float* xp  = (const float*)d_in[1];
    const float* w1l = (const float*)d_in[2];
    const float* b1l = (const float*)d_in[3];
    const float* w1r = (const float*)d_in[4];
    const float* w2l = (const float*)d_in[5];
    const float* b2l = (const float*)d_in[6];
    const float* w2r = (const float*)d_in[7];
    const float* wls = (const float*)d_in[8];
    const float* bls = (const float*)d_in[9];
    const float* wlp = (const float*)d_in[10];
    const float* blp = (const float*)d_in[11];
    const int* ss = (const int*)d_in[12];   // [0..NE)=src, [NE..2NE)=dst
    const int* sp = (const int*)d_in[13];
    const int* ps = (const int*)d_in[14];
    const int* pp = (const int*)d_in[15];
    float* out = (float*)d_out;

    k_zero_hist<<<(NSN + 255) / 256, 256>>>();
    k_hist<<<NE / 256, 256>>>(ss + NE, sp + NE, ps + NE, pp + NE);
    k_scan<<<4, 1024>>>();
    k_fill<<<dim3(NE / 256, 4), 256>>>(ss, sp, ps, pp);
    k_agg1<<<dim3((NSN + 7) / 8, 4), 256>>>(xs, xp);
    k_l1nodes<<<dim3((NSN + 255) / 256, 2), 256>>>(xs, xp, w1l, b1l, w1r);
    k_agg2<<<dim3((NSN + 7) / 8, 4), 256>>>();
    k_l2nodes<<<dim3((NSN + 255) / 256, 2), 256>>>(w2l, b2l, w2r);
    k_final<<<(2 * NSN + 255) / 256, 256>>>(wls, bls, wlp, blp, out);
}